// round 3
// baseline (speedup 1.0000x reference)
#include <cuda_runtime.h>
#include <cstdint>

// ---------------------------------------------------------------------------
// TransitionDown: KNN-group -> shared 1x1 conv (Linear) -> BatchNorm -> ReLU
//                 -> max over K, plus new_xyz = xyz[:, :S]
//
// Restructured: y = x @ W^T computed ONCE per input point (8x fewer FLOPs than
// per-group GEMM); BN stats via multiplicity counts; bias cancels; max/relu/BN
// fused into the gather epilogue (h never materialized).
//
// Distance arithmetic bitwise-replicates the reference fp32 pattern:
//   dot = fma(q2,p2, fma(q1,p1, mul(q0,p0)))       (ascending-k FMA gemm)
//   |p|^2 = fma(z,z, fma(y,y, mul(x,x)))           (reduce pattern)
//   d = add(fma(-2, dot, qq), pp)                  (((-2e)+qq)+pp, contracted)
// so top_k indices match the reference exactly (stable '<' insertion = top_k
// lowest-index tie-break).
// ---------------------------------------------------------------------------

#define BATCH 8
#define NPTS  4096
#define SQ    2048        // N/2 sampled queries
#define KNN   16
#define CIN   128
#define COUT  256
#define NROWS (BATCH * NPTS)   // 32768 input points
#define NQ    (BATCH * SQ)     // 16384 queries
#define BN_EPS 1e-5f

// ---- device scratch (static: no allocations allowed) ----------------------
__device__ float g_y[(size_t)NROWS * COUT];   // 33.5 MB: per-point linear output
__device__ int   g_idx[(size_t)NQ * KNN];     // KNN indices
__device__ int   g_cnt[NROWS];                // selection multiplicity
__device__ float g_psum[256 * COUT];          // per-block partial weighted sums
__device__ float g_psumsq[256 * COUT];
__device__ float g_scale[COUT];
__device__ float g_shift[COUT];

// ---------------------------------------------------------------------------
__global__ void k_zero_cnt() {
    int i = blockIdx.x * blockDim.x + threadIdx.x;
    if (i < NROWS) g_cnt[i] = 0;
}

// ---------------------------------------------------------------------------
// KNN: one thread per query. xyz[b] staged in shared as float4(x,y,z,|p|^2).
// Register-resident sorted top-16. Emits new_xyz and multiplicity counts.
// ---------------------------------------------------------------------------
__global__ void __launch_bounds__(128) k_knn(const float* __restrict__ xyz,
                                             float* __restrict__ out_xyz,
                                             int write_xyz) {
    extern __shared__ float4 sp[];                 // 4096 * 16B = 64 KB
    const int b     = blockIdx.x >> 4;             // 16 blocks / batch
    const int sbase = (blockIdx.x & 15) * 128;
    const int tid   = threadIdx.x;

    for (int i = tid; i < NPTS; i += 128) {
        const float* p = xyz + ((size_t)b * NPTS + i) * 3;
        float px = p[0], py = p[1], pz = p[2];
        // |p|^2 exactly as reference reduce: fma(z,z, fma(y,y, x*x))
        float pw = __fmaf_rn(pz, pz, __fmaf_rn(py, py, __fmul_rn(px, px)));
        sp[i] = make_float4(px, py, pz, pw);
    }
    __syncthreads();

    const int s = sbase + tid;                     // s < 2048 < 4096
    const float4 q = sp[s];

    float best[KNN];
    int   bidx[KNN];
#pragma unroll
    for (int t = 0; t < KNN; ++t) { best[t] = 3.4e38f; bidx[t] = 0; }

    for (int n = 0; n < NPTS; ++n) {
        float4 p = sp[n];
        // dot exactly as ascending-k FMA accumulation
        float dot = __fmaf_rn(q.z, p.z,
                    __fmaf_rn(q.y, p.y,
                    __fmul_rn(q.x, p.x)));
        // d = ((-2*dot) + qq) + pp with mul+add contracted to fma
        float d = __fadd_rn(__fmaf_rn(-2.0f, dot, q.w), p.w);
        if (d < best[KNN - 1]) {
            float cd = d; int ci = n;
#pragma unroll
            for (int t = 0; t < KNN; ++t) {
                if (cd < best[t]) {
                    float td = best[t]; best[t] = cd; cd = td;
                    int   ti = bidx[t]; bidx[t] = ci; ci = ti;
                }
            }
        }
    }

    const size_t gi = ((size_t)b * SQ + s) * KNN;
#pragma unroll
    for (int t = 0; t < KNN; ++t) {
        g_idx[gi + t] = bidx[t];
        atomicAdd(&g_cnt[b * NPTS + bidx[t]], 1);
    }

    if (write_xyz) {
        float* o = out_xyz + ((size_t)b * SQ + s) * 3;
        o[0] = q.x; o[1] = q.y; o[2] = q.z;
    }
}

// ---------------------------------------------------------------------------
// SGEMM: y[32768, 256] = x[32768, 128] @ W[256, 128]^T  (fp32, no bias)
// 128x128x128 block tile, 256 threads, 8x8 microtiles, smem stored k-major.
// ---------------------------------------------------------------------------
__global__ void __launch_bounds__(256) k_gemm(const float* __restrict__ x,
                                              const float* __restrict__ W) {
    extern __shared__ float sm[];
    float* Xs = sm;                    // [128][128]  Xs[c*128 + m]
    float* Ws = sm + 128 * 128;        // [128][128]  Ws[c*128 + n]

    const int tid   = threadIdx.x;
    const int mbase = blockIdx.x * 128;
    const int nbase = blockIdx.y * 128;

    for (int e = tid; e < 4096; e += 256) {
        int c4 = e >> 7, m = e & 127;
        float4 v = *(const float4*)(x + (size_t)(mbase + m) * CIN + c4 * 4);
        Xs[(c4 * 4 + 0) * 128 + m] = v.x;
        Xs[(c4 * 4 + 1) * 128 + m] = v.y;
        Xs[(c4 * 4 + 2) * 128 + m] = v.z;
        Xs[(c4 * 4 + 3) * 128 + m] = v.w;
    }
    for (int e = tid; e < 4096; e += 256) {
        int c4 = e >> 7, n = e & 127;
        float4 v = *(const float4*)(W + (size_t)(nbase + n) * CIN + c4 * 4);
        Ws[(c4 * 4 + 0) * 128 + n] = v.x;
        Ws[(c4 * 4 + 1) * 128 + n] = v.y;
        Ws[(c4 * 4 + 2) * 128 + n] = v.z;
        Ws[(c4 * 4 + 3) * 128 + n] = v.w;
    }
    __syncthreads();

    const int w    = tid >> 5;
    const int lane = tid & 31;
    const int m0 = (w & 1) * 64 + (lane & 7) * 8;   // warp grid 2(m) x 4(n)
    const int n0 = (w >> 1) * 32 + (lane >> 3) * 8; // lane grid 8(m) x 4(n)

    float acc[8][8];
#pragma unroll
    for (int i = 0; i < 8; ++i)
#pragma unroll
        for (int j = 0; j < 8; ++j) acc[i][j] = 0.0f;

#pragma unroll 4
    for (int c = 0; c < CIN; ++c) {
        float a[8], bb[8];
        *(float4*)(a)      = *(const float4*)(Xs + c * 128 + m0);
        *(float4*)(a + 4)  = *(const float4*)(Xs + c * 128 + m0 + 4);
        *(float4*)(bb)     = *(const float4*)(Ws + c * 128 + n0);
        *(float4*)(bb + 4) = *(const float4*)(Ws + c * 128 + n0 + 4);
#pragma unroll
        for (int i = 0; i < 8; ++i)
#pragma unroll
            for (int j = 0; j < 8; ++j)
                acc[i][j] = fmaf(a[i], bb[j], acc[i][j]);
    }

#pragma unroll
    for (int i = 0; i < 8; ++i) {
        float* dst = g_y + (size_t)(mbase + m0 + i) * COUT + nbase + n0;
        *(float4*)(dst)     = make_float4(acc[i][0], acc[i][1], acc[i][2], acc[i][3]);
        *(float4*)(dst + 4) = make_float4(acc[i][4], acc[i][5], acc[i][6], acc[i][7]);
    }
}

// ---------------------------------------------------------------------------
// Multiplicity-weighted per-channel partial sums (deterministic two-level
// reduction: 256 blocks x 128 rows -> partials, reduced in k_finalize).
// ---------------------------------------------------------------------------
__global__ void __launch_bounds__(256) k_stats() {
    const int o = threadIdx.x;
    const int rbase = blockIdx.x * 128;
    float s = 0.0f, sq = 0.0f;
    for (int i = 0; i < 128; ++i) {
        int row = rbase + i;
        float c = (float)g_cnt[row];
        float v = g_y[(size_t)row * COUT + o];
        s  += c * v;
        sq += c * v * v;
    }
    g_psum[blockIdx.x * COUT + o]   = s;
    g_psumsq[blockIdx.x * COUT + o] = sq;
}

__global__ void k_finalize(const float* __restrict__ gamma,
                           const float* __restrict__ beta) {
    const int o = threadIdx.x;   // 1 block, 256 threads
    float s = 0.0f, sq = 0.0f;
    for (int r = 0; r < 256; ++r) {
        s  += g_psum[r * COUT + o];
        sq += g_psumsq[r * COUT + o];
    }
    const float invn = 1.0f / (float)((size_t)NQ * KNN);
    float mean = s * invn;
    float var  = sq * invn - mean * mean;     // population var; bias-invariant
    float inv  = rsqrtf(var + BN_EPS);
    float sc   = gamma[o] * inv;
    g_scale[o] = sc;
    g_shift[o] = beta[o] - mean * sc;         // bias b cancels exactly
}

// ---------------------------------------------------------------------------
// Fused gather + max/min over K + BN affine + ReLU. One block per (b,s),
// thread = output channel; 16 coalesced y-row gathers (mostly L2 hits).
// max commutes with the monotone affine: use min when scale < 0.
// ---------------------------------------------------------------------------
__global__ void __launch_bounds__(256) k_pool(float* __restrict__ out) {
    __shared__ int sidx[KNN];
    const int blk = blockIdx.x;           // b*SQ + s
    const int o   = threadIdx.x;
    if (o < KNN) sidx[o] = g_idx[(size_t)blk * KNN + o];
    __syncthreads();

    const int b = blk >> 11;              // / SQ
    const float* yb = g_y + (size_t)b * NPTS * COUT;

    float mx = -3.4e38f, mn = 3.4e38f;
#pragma unroll
    for (int k = 0; k < KNN; ++k) {
        float v = yb[(size_t)sidx[k] * COUT + o];
        mx = fmaxf(mx, v);
        mn = fminf(mn, v);
    }
    const float sc = g_scale[o];
    const float v  = (sc >= 0.0f) ? mx : mn;
    out[(size_t)blk * COUT + o] = fmaxf(fmaf(v, sc, g_shift[o]), 0.0f);
}

// ---------------------------------------------------------------------------
extern "C" void kernel_launch(void* const* d_in, const int* in_sizes, int n_in,
                              void* d_out, int out_size) {
    const float* x     = (const float*)d_in[0];   // (8,4096,128)
    const float* xyz   = (const float*)d_in[1];   // (8,4096,3)
    const float* W     = (const float*)d_in[2];   // (256,128)
    // d_in[3] = bias: cancels analytically, unused
    const float* gamma = (const float*)d_in[4];
    const float* beta  = (const float*)d_in[5];
    float* out = (float*)d_out;

    const int np_elems  = NQ * COUT;              // 4,194,304
    const int xyz_elems = NQ * 3;                 // 49,152
    const int write_xyz = (out_size >= np_elems + xyz_elems) ? 1 : 0;
    float* out_xyz = out + np_elems;

    cudaFuncSetAttribute(k_knn,  cudaFuncAttributeMaxDynamicSharedMemorySize,
                         NPTS * (int)sizeof(float4));                  // 64 KB
    cudaFuncSetAttribute(k_gemm, cudaFuncAttributeMaxDynamicSharedMemorySize,
                         2 * 128 * 128 * (int)sizeof(float));          // 128 KB

    k_zero_cnt<<<(NROWS + 255) / 256, 256>>>();
    k_knn<<<BATCH * (SQ / 128), 128, NPTS * sizeof(float4)>>>(xyz, out_xyz, write_xyz);
    dim3 gg(NROWS / 128, COUT / 128);              // 256 x 2 blocks
    k_gemm<<<gg, 256, 2 * 128 * 128 * sizeof(float)>>>(x, W);
    k_stats<<<NROWS / 128, COUT>>>();
    k_finalize<<<1, COUT>>>(gamma, beta);
    k_pool<<<NQ, COUT>>>(out);
}

// round 4
// speedup vs baseline: 1.3615x; 1.3615x over previous
#include <cuda_runtime.h>
#include <cstdint>

// ---------------------------------------------------------------------------
// TransitionDown: KNN-group -> shared Linear -> BN -> ReLU -> max over K.
// y = x@W^T once per input point; BN stats via multiplicity counts (fused into
// GEMM epilogue); bias cancels; max commutes with monotone BN affine.
// KNN: 4-way candidate split per query + exact tie-preserving merge.
// GEMM: fp32x2 packed FMA (FFMA2), 2 FLOPs/instr.
// ---------------------------------------------------------------------------

#define BATCH 8
#define NPTS  4096
#define SQ    2048
#define KNN   16
#define CIN   128
#define COUT  256
#define NROWS (BATCH * NPTS)   // 32768
#define NQ    (BATCH * SQ)     // 16384
#define BN_EPS 1e-5f

__device__ float g_y[(size_t)NROWS * COUT];   // 33.5 MB
__device__ int   g_idx[(size_t)NQ * KNN];
__device__ int   g_cnt[NROWS];
__device__ float g_psum[256 * COUT];
__device__ float g_psumsq[256 * COUT];
__device__ float g_scale[COUT];
__device__ float g_shift[COUT];

#define FMA2(d, a, b, c) \
    asm("fma.rn.f32x2 %0, %1, %2, %3;" : "=l"(d) : "l"(a), "l"(b), "l"(c))
#define DUP2(d, a) \
    asm("mov.b64 %0, {%1, %1};" : "=l"(d) : "r"(a))
#define UNPK2(lo, hi, v) \
    asm("mov.b64 {%0, %1}, %2;" : "=f"(lo), "=f"(hi) : "l"(v))

// ---------------------------------------------------------------------------
__global__ void k_zero_cnt() {
    int i = blockIdx.x * blockDim.x + threadIdx.x;
    if (i < NROWS) g_cnt[i] = 0;
}

// ---------------------------------------------------------------------------
// KNN: 256 threads = 64 queries x 4 candidate segments (1024 each).
// Distance arithmetic bitwise-replicates the reference fp32 pattern:
//   dot = fma(q2,p2, fma(q1,p1, mul(q0,p0)))
//   |p|^2 = fma(z,z, fma(y,y, x*x))
//   d = add(fma(-2, dot, qq), pp)
// Per-thread strict-'<' sorted top-16 (stable index order), then a 4-pointer
// merge preferring lower segment on ties -> identical selection to a single
// full-range scan (= reference top_k tie behavior).
// ---------------------------------------------------------------------------
__global__ void __launch_bounds__(256) k_knn(const float* __restrict__ xyz,
                                             float* __restrict__ out_xyz,
                                             int write_xyz) {
    extern __shared__ float4 sp[];                 // 4096 * 16B
    float* md = (float*)(sp + NPTS);               // [64][4][16] distances
    int*   mi = (int*)(md + 64 * 64);              // [64][4][16] indices

    const int b     = blockIdx.x >> 5;             // 32 blocks / batch
    const int sbase = (blockIdx.x & 31) * 64;
    const int tid   = threadIdx.x;
    const int seg   = tid >> 6;                    // 0..3
    const int q     = tid & 63;                    // 0..63

    for (int i = tid; i < NPTS; i += 256) {
        const float* p = xyz + ((size_t)b * NPTS + i) * 3;
        float px = p[0], py = p[1], pz = p[2];
        float pw = __fmaf_rn(pz, pz, __fmaf_rn(py, py, __fmul_rn(px, px)));
        sp[i] = make_float4(px, py, pz, pw);
    }
    __syncthreads();

    const int s = sbase + q;
    const float4 qq = sp[s];

    float best[KNN];
    int   bidx[KNN];
#pragma unroll
    for (int t = 0; t < KNN; ++t) { best[t] = 3.4e38f; bidx[t] = 0; }

    const int nbeg = seg * (NPTS / 4);
#pragma unroll 2
    for (int n = nbeg; n < nbeg + NPTS / 4; ++n) {
        float4 p = sp[n];
        float dot = __fmaf_rn(qq.z, p.z,
                    __fmaf_rn(qq.y, p.y,
                    __fmul_rn(qq.x, p.x)));
        float d = __fadd_rn(__fmaf_rn(-2.0f, dot, qq.w), p.w);
        if (d < best[KNN - 1]) {
            float cd = d; int ci = n;
#pragma unroll
            for (int t = 0; t < KNN; ++t) {
                if (cd < best[t]) {
                    float td = best[t]; best[t] = cd; cd = td;
                    int   ti = bidx[t]; bidx[t] = ci; ci = ti;
                }
            }
        }
    }

    float* mdq = md + q * 64 + seg * 16;
    int*   miq = mi + q * 64 + seg * 16;
#pragma unroll
    for (int t = 0; t < KNN; ++t) { mdq[t] = best[t]; miq[t] = bidx[t]; }
    __syncthreads();

    if (seg == 0) {
        int ptr0 = 0, ptr1 = 0, ptr2 = 0, ptr3 = 0;
        const float* m0 = md + q * 64;
        const int*   i0 = mi + q * 64;
        const size_t gi = ((size_t)b * SQ + s) * KNN;
#pragma unroll
        for (int t = 0; t < KNN; ++t) {
            float bd = m0[ptr0]; int bs = 0;
            float d1 = m0[16 + ptr1]; if (d1 < bd) { bd = d1; bs = 1; }
            float d2 = m0[32 + ptr2]; if (d2 < bd) { bd = d2; bs = 2; }
            float d3 = m0[48 + ptr3]; if (d3 < bd) { bd = d3; bs = 3; }
            int id;
            if      (bs == 0) { id = i0[ptr0];      ptr0++; }
            else if (bs == 1) { id = i0[16 + ptr1]; ptr1++; }
            else if (bs == 2) { id = i0[32 + ptr2]; ptr2++; }
            else              { id = i0[48 + ptr3]; ptr3++; }
            g_idx[gi + t] = id;
            atomicAdd(&g_cnt[b * NPTS + id], 1);
        }
        if (write_xyz) {
            float* o = out_xyz + ((size_t)b * SQ + s) * 3;
            o[0] = qq.x; o[1] = qq.y; o[2] = qq.z;
        }
    }
}

// ---------------------------------------------------------------------------
// SGEMM + fused weighted-BN-stats: y[32768,256] = x @ W^T (fp32, no bias).
// 128x128x128 tile, 256 threads, 8x8 microtile as 8x4 f32x2 accumulators.
// Identical FMA ordering per element to scalar version (bitwise-same y).
// ---------------------------------------------------------------------------
__global__ void __launch_bounds__(256) k_gemm(const float* __restrict__ x,
                                              const float* __restrict__ W) {
    extern __shared__ float sm[];
    float* Xs = sm;                    // [128][128]  Xs[c*128+m]
    float* Ws = sm + 128 * 128;        // [128][128]  Ws[c*128+n]

    const int tid   = threadIdx.x;
    const int mbase = blockIdx.x * 128;
    const int nbase = blockIdx.y * 128;

    for (int e = tid; e < 4096; e += 256) {
        int c4 = e >> 7, m = e & 127;
        float4 v = *(const float4*)(x + (size_t)(mbase + m) * CIN + c4 * 4);
        Xs[(c4 * 4 + 0) * 128 + m] = v.x;
        Xs[(c4 * 4 + 1) * 128 + m] = v.y;
        Xs[(c4 * 4 + 2) * 128 + m] = v.z;
        Xs[(c4 * 4 + 3) * 128 + m] = v.w;
    }
    for (int e = tid; e < 4096; e += 256) {
        int c4 = e >> 7, n = e & 127;
        float4 v = *(const float4*)(W + (size_t)(nbase + n) * CIN + c4 * 4);
        Ws[(c4 * 4 + 0) * 128 + n] = v.x;
        Ws[(c4 * 4 + 1) * 128 + n] = v.y;
        Ws[(c4 * 4 + 2) * 128 + n] = v.z;
        Ws[(c4 * 4 + 3) * 128 + n] = v.w;
    }
    __syncthreads();

    const int w    = tid >> 5;
    const int lane = tid & 31;
    const int m0 = (w & 1) * 64 + (lane & 7) * 8;
    const int n0 = (w >> 1) * 32 + (lane >> 3) * 8;
    const int grp = ((w & 1) << 3) | (lane & 7);    // 16 m-groups

    unsigned long long acc2[8][4];
#pragma unroll
    for (int i = 0; i < 8; ++i)
#pragma unroll
        for (int jp = 0; jp < 4; ++jp) acc2[i][jp] = 0ULL;

#pragma unroll 4
    for (int c = 0; c < CIN; ++c) {
        float a8[8];
        *(float4*)(a8)     = *(const float4*)(Xs + c * 128 + m0);
        *(float4*)(a8 + 4) = *(const float4*)(Xs + c * 128 + m0 + 4);
        ulonglong2 b01 = *(const ulonglong2*)(Ws + c * 128 + n0);
        ulonglong2 b23 = *(const ulonglong2*)(Ws + c * 128 + n0 + 4);
        unsigned long long bb0 = b01.x, bb1 = b01.y, bb2 = b23.x, bb3 = b23.y;
#pragma unroll
        for (int i = 0; i < 8; ++i) {
            unsigned long long aa;
            DUP2(aa, __float_as_uint(a8[i]));
            FMA2(acc2[i][0], aa, bb0, acc2[i][0]);
            FMA2(acc2[i][1], aa, bb1, acc2[i][1]);
            FMA2(acc2[i][2], aa, bb2, acc2[i][2]);
            FMA2(acc2[i][3], aa, bb3, acc2[i][3]);
        }
    }

    float acc[8][8];
#pragma unroll
    for (int i = 0; i < 8; ++i)
#pragma unroll
        for (int jp = 0; jp < 4; ++jp)
            UNPK2(acc[i][2 * jp], acc[i][2 * jp + 1], acc2[i][jp]);

#pragma unroll
    for (int i = 0; i < 8; ++i) {
        float* dst = g_y + (size_t)(mbase + m0 + i) * COUT + nbase + n0;
        *(float4*)(dst)     = make_float4(acc[i][0], acc[i][1], acc[i][2], acc[i][3]);
        *(float4*)(dst + 4) = make_float4(acc[i][4], acc[i][5], acc[i][6], acc[i][7]);
    }

    // ---- fused weighted BN stats: per-column cnt-weighted sum & sumsq -----
    float cw[8];
#pragma unroll
    for (int i = 0; i < 8; ++i) cw[i] = (float)g_cnt[mbase + m0 + i];

    float s[8], sq[8];
#pragma unroll
    for (int j = 0; j < 8; ++j) { s[j] = 0.0f; sq[j] = 0.0f; }
#pragma unroll
    for (int i = 0; i < 8; ++i)
#pragma unroll
        for (int j = 0; j < 8; ++j) {
            float v = acc[i][j];
            s[j]  = fmaf(cw[i], v, s[j]);
            sq[j] = fmaf(cw[i] * v, v, sq[j]);
        }

    __syncthreads();                       // smem free for reduction buffers
    float* red  = sm;                      // [(n)*17 + grp], n<128
    float* red2 = sm + 128 * 17;
#pragma unroll
    for (int j = 0; j < 8; ++j) {
        red [(n0 + j) * 17 + grp] = s[j];
        red2[(n0 + j) * 17 + grp] = sq[j];
    }
    __syncthreads();

    {
        int col  = tid & 127;
        const float* src = (tid < 128) ? red : red2;
        float acc1 = 0.0f;
#pragma unroll
        for (int g = 0; g < 16; ++g) acc1 += src[col * 17 + g];
        float* dst = (tid < 128) ? g_psum : g_psumsq;
        dst[blockIdx.x * COUT + nbase + col] = acc1;
    }
}

// ---------------------------------------------------------------------------
__global__ void k_finalize(const float* __restrict__ gamma,
                           const float* __restrict__ beta) {
    const int o = threadIdx.x;   // 1 block, 256 threads
    float s = 0.0f, sq = 0.0f;
    for (int r = 0; r < 256; ++r) {
        s  += g_psum[r * COUT + o];
        sq += g_psumsq[r * COUT + o];
    }
    const float invn = 1.0f / (float)((size_t)NQ * KNN);
    float mean = s * invn;
    float var  = sq * invn - mean * mean;
    float inv  = rsqrtf(var + BN_EPS);
    float sc   = gamma[o] * inv;
    g_scale[o] = sc;
    g_shift[o] = beta[o] - mean * sc;
}

// ---------------------------------------------------------------------------
// Fused gather + max/min over K + BN affine + ReLU. Block = 4 queries,
// 64 threads/query, float4 over 256 channels (L2-resident gathers).
// ---------------------------------------------------------------------------
__global__ void __launch_bounds__(256) k_pool(float* __restrict__ out) {
    __shared__ int sidx[64];
    const int tid = threadIdx.x;
    if (tid < 64) sidx[tid] = g_idx[(size_t)blockIdx.x * 64 + tid];
    __syncthreads();

    const int qi = tid >> 6;               // 0..3
    const int c4 = tid & 63;               // float4 lane over 256 ch
    const int q  = blockIdx.x * 4 + qi;
    const int b  = q >> 11;
    const float4* yb = (const float4*)g_y + (size_t)b * NPTS * 64;

    float4 mx = make_float4(-3.4e38f, -3.4e38f, -3.4e38f, -3.4e38f);
    float4 mn = make_float4( 3.4e38f,  3.4e38f,  3.4e38f,  3.4e38f);
#pragma unroll
    for (int k = 0; k < KNN; ++k) {
        float4 v = yb[(size_t)sidx[qi * 16 + k] * 64 + c4];
        mx.x = fmaxf(mx.x, v.x); mn.x = fminf(mn.x, v.x);
        mx.y = fmaxf(mx.y, v.y); mn.y = fminf(mn.y, v.y);
        mx.z = fmaxf(mx.z, v.z); mn.z = fminf(mn.z, v.z);
        mx.w = fmaxf(mx.w, v.w); mn.w = fminf(mn.w, v.w);
    }
    float4 sc = ((const float4*)g_scale)[c4];
    float4 sh = ((const float4*)g_shift)[c4];
    float4 r;
    r.x = fmaxf(fmaf(sc.x >= 0.f ? mx.x : mn.x, sc.x, sh.x), 0.f);
    r.y = fmaxf(fmaf(sc.y >= 0.f ? mx.y : mn.y, sc.y, sh.y), 0.f);
    r.z = fmaxf(fmaf(sc.z >= 0.f ? mx.z : mn.z, sc.z, sh.z), 0.f);
    r.w = fmaxf(fmaf(sc.w >= 0.f ? mx.w : mn.w, sc.w, sh.w), 0.f);
    ((float4*)out)[(size_t)q * 64 + c4] = r;
}

// ---------------------------------------------------------------------------
extern "C" void kernel_launch(void* const* d_in, const int* in_sizes, int n_in,
                              void* d_out, int out_size) {
    const float* x     = (const float*)d_in[0];
    const float* xyz   = (const float*)d_in[1];
    const float* W     = (const float*)d_in[2];
    // d_in[3] = bias: cancels analytically
    const float* gamma = (const float*)d_in[4];
    const float* beta  = (const float*)d_in[5];
    float* out = (float*)d_out;

    const int np_elems  = NQ * COUT;
    const int xyz_elems = NQ * 3;
    const int write_xyz = (out_size >= np_elems + xyz_elems) ? 1 : 0;
    float* out_xyz = out + np_elems;

    const int knn_smem  = NPTS * (int)sizeof(float4) + 64 * 64 * 8; // 96 KB
    const int gemm_smem = 2 * 128 * 128 * (int)sizeof(float);        // 128 KB
    cudaFuncSetAttribute(k_knn,  cudaFuncAttributeMaxDynamicSharedMemorySize, knn_smem);
    cudaFuncSetAttribute(k_gemm, cudaFuncAttributeMaxDynamicSharedMemorySize, gemm_smem);

    k_zero_cnt<<<(NROWS + 255) / 256, 256>>>();
    k_knn<<<BATCH * (SQ / 64), 256, knn_smem>>>(xyz, out_xyz, write_xyz);
    dim3 gg(NROWS / 128, COUT / 128);
    k_gemm<<<gg, 256, gemm_smem>>>(x, W);
    k_finalize<<<1, COUT>>>(gamma, beta);
    k_pool<<<NQ / 4, 256>>>(out);
}

// round 5
// speedup vs baseline: 2.6917x; 1.9770x over previous
#include <cuda_runtime.h>
#include <cstdint>

// ---------------------------------------------------------------------------
// TransitionDown: KNN-group -> shared Linear -> BN -> ReLU -> max over K.
// y = x@W^T once per input point; BN stats via multiplicity counts (fused into
// GEMM epilogue); bias cancels; max commutes with monotone BN affine.
// KNN: exact threshold-filtered two-pass (branchless pass A slot-minima ->
//      provable upper bound T on the 16th distance -> tiny survivor list ->
//      exact ordered insertion), replacing the divergent 16-deep insert.
// ---------------------------------------------------------------------------

#define BATCH 8
#define NPTS  4096
#define SQ    2048
#define KNN   16
#define CIN   128
#define COUT  256
#define NROWS (BATCH * NPTS)   // 32768
#define NQ    (BATCH * SQ)     // 16384
#define BN_EPS 1e-5f
#define SEGN  1024             // candidates per thread (4 segments)
#define BUFCAP 64

__device__ float  g_y[(size_t)NROWS * COUT];          // 33.5 MB
__device__ int    g_idx[(size_t)NQ * KNN];
__device__ int    g_cnt[NROWS];                       // zero at load + by k_pool
__device__ float  g_psum[256 * COUT];
__device__ float  g_psumsq[256 * COUT];
__device__ float  g_scale[COUT];
__device__ float  g_shift[COUT];
__device__ float2 g_buf[(size_t)NQ * 4 * BUFCAP];     // 33.5 MB survivor scratch

#define FMA2(d, a, b, c) \
    asm("fma.rn.f32x2 %0, %1, %2, %3;" : "=l"(d) : "l"(a), "l"(b), "l"(c))
#define DUP2(d, a) \
    asm("mov.b64 %0, {%1, %1};" : "=l"(d) : "r"(a))
#define UNPK2(lo, hi, v) \
    asm("mov.b64 {%0, %1}, %2;" : "=f"(lo), "=f"(hi) : "l"(v))

// Distance bitwise-replicating the reference fp32 pattern.
#define DIST(qq, p) \
    __fadd_rn(__fmaf_rn(-2.0f, \
        __fmaf_rn((qq).z, (p).z, __fmaf_rn((qq).y, (p).y, __fmul_rn((qq).x, (p).x))), \
        (qq).w), (p).w)

// ---------------------------------------------------------------------------
// KNN: 256 blocks x 256 threads = 64 queries x 4 segments (1024 cand each).
// ---------------------------------------------------------------------------
__global__ void __launch_bounds__(256) k_knn(const float* __restrict__ xyz,
                                             float* __restrict__ out_xyz,
                                             int write_xyz) {
    extern __shared__ float4 sp[];                 // 4096*16B = 64 KB
    float* md = (float*)(sp + NPTS);               // [64][4][16]
    int*   mi = (int*)(md + 64 * 64);              // [64][4][16]

    const int b     = blockIdx.x >> 5;             // 32 blocks / batch
    const int sbase = (blockIdx.x & 31) * 64;
    const int tid   = threadIdx.x;
    const int seg   = tid >> 6;                    // 0..3
    const int q     = tid & 63;                    // 0..63

    for (int i = tid; i < NPTS; i += 256) {
        const float* p = xyz + ((size_t)b * NPTS + i) * 3;
        float px = p[0], py = p[1], pz = p[2];
        float pw = __fmaf_rn(pz, pz, __fmaf_rn(py, py, __fmul_rn(px, px)));
        sp[i] = make_float4(px, py, pz, pw);
    }
    __syncthreads();

    const int s = sbase + q;
    const float4 qq = sp[s];
    const int nbeg = seg * SEGN;

    // ---- Pass A: branchless 32 slot-minima over this thread's 1024 cands --
    float v[32];
#pragma unroll
    for (int j = 0; j < 32; ++j) v[j] = 3.4e38f;
    for (int nb = 0; nb < SEGN; nb += 32) {
#pragma unroll
        for (int j = 0; j < 32; ++j) {
            float4 p = sp[nbeg + nb + j];
            float d = DIST(qq, p);
            v[j] = fminf(v[j], d);
        }
    }

    // ---- T = 16th smallest of 32 slot-minima (register bitonic sort) ------
#pragma unroll
    for (int k = 2; k <= 32; k <<= 1) {
#pragma unroll
        for (int j = k >> 1; j > 0; j >>= 1) {
#pragma unroll
            for (int i = 0; i < 32; ++i) {
                int l = i ^ j;
                if (l > i) {
                    bool up = ((i & k) == 0);
                    float lo = fminf(v[i], v[l]);
                    float hi = fmaxf(v[i], v[l]);
                    v[i] = up ? lo : hi;
                    v[l] = up ? hi : lo;
                }
            }
        }
    }
    const float T = v[15];   // >= true 16th-smallest of this thread's range

    // ---- Pass B: collect survivors (d <= T) in index order ----------------
    const size_t bbase = ((size_t)blockIdx.x * 256 + tid) * BUFCAP;
    int cnt = 0;
    for (int n = nbeg; n < nbeg + SEGN; ++n) {
        float4 p = sp[n];
        float d = DIST(qq, p);
        if (d <= T) {
            if (cnt < BUFCAP)
                g_buf[bbase + cnt] = make_float2(d, __int_as_float(n));
            cnt++;
        }
    }

    // ---- Exact top-16 among survivors (strict-'<' stable insertion) -------
    float best[KNN];
    int   bidx[KNN];
#pragma unroll
    for (int t = 0; t < KNN; ++t) { best[t] = 3.4e38f; bidx[t] = 0; }

    if (cnt <= BUFCAP) {
        for (int i = 0; i < cnt; ++i) {
            float2 e = g_buf[bbase + i];
            float cd = e.x;
            if (cd < best[KNN - 1]) {
                int ci = __float_as_int(e.y);
#pragma unroll
                for (int t = 0; t < KNN; ++t) {
                    if (cd < best[t]) {
                        float td = best[t]; best[t] = cd; cd = td;
                        int   ti = bidx[t]; bidx[t] = ci; ci = ti;
                    }
                }
            }
        }
    } else {
        // overflow fallback (astronomically rare): classic exact full scan
        for (int n = nbeg; n < nbeg + SEGN; ++n) {
            float4 p = sp[n];
            float d = DIST(qq, p);
            if (d < best[KNN - 1]) {
                float cd = d; int ci = n;
#pragma unroll
                for (int t = 0; t < KNN; ++t) {
                    if (cd < best[t]) {
                        float td = best[t]; best[t] = cd; cd = td;
                        int   ti = bidx[t]; bidx[t] = ci; ci = ti;
                    }
                }
            }
        }
    }

    float* mdq = md + q * 64 + seg * 16;
    int*   miq = mi + q * 64 + seg * 16;
#pragma unroll
    for (int t = 0; t < KNN; ++t) { mdq[t] = best[t]; miq[t] = bidx[t]; }
    __syncthreads();

    // ---- 4-way tie-preserving merge (seg 0 threads) -----------------------
    if (seg == 0) {
        int ptr0 = 0, ptr1 = 0, ptr2 = 0, ptr3 = 0;
        const float* m0 = md + q * 64;
        const int*   i0 = mi + q * 64;
        const size_t gi = ((size_t)b * SQ + s) * KNN;
#pragma unroll
        for (int t = 0; t < KNN; ++t) {
            float bd = m0[ptr0]; int bs = 0;
            float d1 = m0[16 + ptr1]; if (d1 < bd) { bd = d1; bs = 1; }
            float d2 = m0[32 + ptr2]; if (d2 < bd) { bd = d2; bs = 2; }
            float d3 = m0[48 + ptr3]; if (d3 < bd) { bd = d3; bs = 3; }
            int id;
            if      (bs == 0) { id = i0[ptr0];      ptr0++; }
            else if (bs == 1) { id = i0[16 + ptr1]; ptr1++; }
            else if (bs == 2) { id = i0[32 + ptr2]; ptr2++; }
            else              { id = i0[48 + ptr3]; ptr3++; }
            g_idx[gi + t] = id;
            atomicAdd(&g_cnt[b * NPTS + id], 1);
        }
        if (write_xyz) {
            float* o = out_xyz + ((size_t)b * SQ + s) * 3;
            o[0] = qq.x; o[1] = qq.y; o[2] = qq.z;
        }
    }
}

// ---------------------------------------------------------------------------
// SGEMM + fused weighted-BN-stats: y = x @ W^T (fp32, FFMA2 accumulators).
// ---------------------------------------------------------------------------
__global__ void __launch_bounds__(256) k_gemm(const float* __restrict__ x,
                                              const float* __restrict__ W) {
    extern __shared__ float sm[];
    float* Xs = sm;                    // [128][128]  Xs[c*128+m]
    float* Ws = sm + 128 * 128;        // [128][128]  Ws[c*128+n]

    const int tid   = threadIdx.x;
    const int mbase = blockIdx.x * 128;
    const int nbase = blockIdx.y * 128;

    for (int e = tid; e < 4096; e += 256) {
        int c4 = e >> 7, m = e & 127;
        float4 v = *(const float4*)(x + (size_t)(mbase + m) * CIN + c4 * 4);
        Xs[(c4 * 4 + 0) * 128 + m] = v.x;
        Xs[(c4 * 4 + 1) * 128 + m] = v.y;
        Xs[(c4 * 4 + 2) * 128 + m] = v.z;
        Xs[(c4 * 4 + 3) * 128 + m] = v.w;
    }
    for (int e = tid; e < 4096; e += 256) {
        int c4 = e >> 7, n = e & 127;
        float4 v = *(const float4*)(W + (size_t)(nbase + n) * CIN + c4 * 4);
        Ws[(c4 * 4 + 0) * 128 + n] = v.x;
        Ws[(c4 * 4 + 1) * 128 + n] = v.y;
        Ws[(c4 * 4 + 2) * 128 + n] = v.z;
        Ws[(c4 * 4 + 3) * 128 + n] = v.w;
    }
    __syncthreads();

    const int w    = tid >> 5;
    const int lane = tid & 31;
    const int m0 = (w & 1) * 64 + (lane & 7) * 8;
    const int n0 = (w >> 1) * 32 + (lane >> 3) * 8;
    const int grp = ((w & 1) << 3) | (lane & 7);    // 16 m-groups

    unsigned long long acc2[8][4];
#pragma unroll
    for (int i = 0; i < 8; ++i)
#pragma unroll
        for (int jp = 0; jp < 4; ++jp) acc2[i][jp] = 0ULL;

#pragma unroll 4
    for (int c = 0; c < CIN; ++c) {
        float a8[8];
        *(float4*)(a8)     = *(const float4*)(Xs + c * 128 + m0);
        *(float4*)(a8 + 4) = *(const float4*)(Xs + c * 128 + m0 + 4);
        ulonglong2 b01 = *(const ulonglong2*)(Ws + c * 128 + n0);
        ulonglong2 b23 = *(const ulonglong2*)(Ws + c * 128 + n0 + 4);
        unsigned long long bb0 = b01.x, bb1 = b01.y, bb2 = b23.x, bb3 = b23.y;
#pragma unroll
        for (int i = 0; i < 8; ++i) {
            unsigned long long aa;
            DUP2(aa, __float_as_uint(a8[i]));
            FMA2(acc2[i][0], aa, bb0, acc2[i][0]);
            FMA2(acc2[i][1], aa, bb1, acc2[i][1]);
            FMA2(acc2[i][2], aa, bb2, acc2[i][2]);
            FMA2(acc2[i][3], aa, bb3, acc2[i][3]);
        }
    }

    float acc[8][8];
#pragma unroll
    for (int i = 0; i < 8; ++i)
#pragma unroll
        for (int jp = 0; jp < 4; ++jp)
            UNPK2(acc[i][2 * jp], acc[i][2 * jp + 1], acc2[i][jp]);

#pragma unroll
    for (int i = 0; i < 8; ++i) {
        float* dst = g_y + (size_t)(mbase + m0 + i) * COUT + nbase + n0;
        *(float4*)(dst)     = make_float4(acc[i][0], acc[i][1], acc[i][2], acc[i][3]);
        *(float4*)(dst + 4) = make_float4(acc[i][4], acc[i][5], acc[i][6], acc[i][7]);
    }

    // ---- fused weighted BN stats ------------------------------------------
    float cw[8];
#pragma unroll
    for (int i = 0; i < 8; ++i) cw[i] = (float)g_cnt[mbase + m0 + i];

    float s[8], sq[8];
#pragma unroll
    for (int j = 0; j < 8; ++j) { s[j] = 0.0f; sq[j] = 0.0f; }
#pragma unroll
    for (int i = 0; i < 8; ++i)
#pragma unroll
        for (int j = 0; j < 8; ++j) {
            float vv = acc[i][j];
            s[j]  = fmaf(cw[i], vv, s[j]);
            sq[j] = fmaf(cw[i] * vv, vv, sq[j]);
        }

    __syncthreads();
    float* red  = sm;                      // [(n)*17 + grp]
    float* red2 = sm + 128 * 17;
#pragma unroll
    for (int j = 0; j < 8; ++j) {
        red [(n0 + j) * 17 + grp] = s[j];
        red2[(n0 + j) * 17 + grp] = sq[j];
    }
    __syncthreads();

    {
        int col  = tid & 127;
        const float* src = (tid < 128) ? red : red2;
        float acc1 = 0.0f;
#pragma unroll
        for (int g = 0; g < 16; ++g) acc1 += src[col * 17 + g];
        float* dst = (tid < 128) ? g_psum : g_psumsq;
        dst[blockIdx.x * COUT + nbase + col] = acc1;
    }
}

// ---------------------------------------------------------------------------
// Finalize: MLP-unrolled (8 independent load streams) -> scale/shift.
// ---------------------------------------------------------------------------
__global__ void k_finalize(const float* __restrict__ gamma,
                           const float* __restrict__ beta) {
    const int o = threadIdx.x;   // 1 block, 256 threads
    float s0 = 0, s1 = 0, s2 = 0, s3 = 0;
    float q0 = 0, q1 = 0, q2 = 0, q3 = 0;
#pragma unroll 8
    for (int r = 0; r < 64; ++r) {
        s0 += g_psum[(4 * r + 0) * COUT + o];
        s1 += g_psum[(4 * r + 1) * COUT + o];
        s2 += g_psum[(4 * r + 2) * COUT + o];
        s3 += g_psum[(4 * r + 3) * COUT + o];
        q0 += g_psumsq[(4 * r + 0) * COUT + o];
        q1 += g_psumsq[(4 * r + 1) * COUT + o];
        q2 += g_psumsq[(4 * r + 2) * COUT + o];
        q3 += g_psumsq[(4 * r + 3) * COUT + o];
    }
    float s  = (s0 + s1) + (s2 + s3);
    float sq = (q0 + q1) + (q2 + q3);
    const float invn = 1.0f / (float)((size_t)NQ * KNN);
    float mean = s * invn;
    float var  = sq * invn - mean * mean;
    float inv  = rsqrtf(var + BN_EPS);
    float sc   = gamma[o] * inv;
    g_scale[o] = sc;
    g_shift[o] = beta[o] - mean * sc;
}

// ---------------------------------------------------------------------------
// Fused gather + max/min over K + BN affine + ReLU; also re-zeroes g_cnt
// for the next launch (module-load init covers the first).
// ---------------------------------------------------------------------------
__global__ void __launch_bounds__(256) k_pool(float* __restrict__ out) {
    __shared__ int sidx[64];
    const int tid = threadIdx.x;
    if (tid < 64) sidx[tid] = g_idx[(size_t)blockIdx.x * 64 + tid];
    __syncthreads();

    const int qi = tid >> 6;               // 0..3
    const int c4 = tid & 63;               // float4 lane over 256 ch
    const int q  = blockIdx.x * 4 + qi;
    const int b  = q >> 11;
    const float4* yb = (const float4*)g_y + (size_t)b * NPTS * 64;

    float4 mx = make_float4(-3.4e38f, -3.4e38f, -3.4e38f, -3.4e38f);
    float4 mn = make_float4( 3.4e38f,  3.4e38f,  3.4e38f,  3.4e38f);
#pragma unroll
    for (int k = 0; k < KNN; ++k) {
        float4 v = yb[(size_t)sidx[qi * 16 + k] * 64 + c4];
        mx.x = fmaxf(mx.x, v.x); mn.x = fminf(mn.x, v.x);
        mx.y = fmaxf(mx.y, v.y); mn.y = fminf(mn.y, v.y);
        mx.z = fmaxf(mx.z, v.z); mn.z = fminf(mn.z, v.z);
        mx.w = fmaxf(mx.w, v.w); mn.w = fminf(mn.w, v.w);
    }
    float4 sc = ((const float4*)g_scale)[c4];
    float4 sh = ((const float4*)g_shift)[c4];
    float4 r;
    r.x = fmaxf(fmaf(sc.x >= 0.f ? mx.x : mn.x, sc.x, sh.x), 0.f);
    r.y = fmaxf(fmaf(sc.y >= 0.f ? mx.y : mn.y, sc.y, sh.y), 0.f);
    r.z = fmaxf(fmaf(sc.z >= 0.f ? mx.z : mn.z, sc.z, sh.z), 0.f);
    r.w = fmaxf(fmaf(sc.w >= 0.f ? mx.w : mn.w, sc.w, sh.w), 0.f);
    ((float4*)out)[(size_t)q * 64 + c4] = r;

    if (tid < 8) g_cnt[blockIdx.x * 8 + tid] = 0;   // 4096 blocks x 8 = 32768
}

// ---------------------------------------------------------------------------
extern "C" void kernel_launch(void* const* d_in, const int* in_sizes, int n_in,
                              void* d_out, int out_size) {
    const float* x     = (const float*)d_in[0];
    const float* xyz   = (const float*)d_in[1];
    const float* W     = (const float*)d_in[2];
    // d_in[3] = bias: cancels analytically
    const float* gamma = (const float*)d_in[4];
    const float* beta  = (const float*)d_in[5];
    float* out = (float*)d_out;

    const int np_elems  = NQ * COUT;
    const int xyz_elems = NQ * 3;
    const int write_xyz = (out_size >= np_elems + xyz_elems) ? 1 : 0;
    float* out_xyz = out + np_elems;

    const int knn_smem  = NPTS * (int)sizeof(float4) + 64 * 64 * 8;  // 96 KB
    const int gemm_smem = 2 * 128 * 128 * (int)sizeof(float);        // 128 KB
    cudaFuncSetAttribute(k_knn,  cudaFuncAttributeMaxDynamicSharedMemorySize, knn_smem);
    cudaFuncSetAttribute(k_gemm, cudaFuncAttributeMaxDynamicSharedMemorySize, gemm_smem);

    k_knn<<<BATCH * (SQ / 64), 256, knn_smem>>>(xyz, out_xyz, write_xyz);
    dim3 gg(NROWS / 128, COUT / 128);
    k_gemm<<<gg, 256, gemm_smem>>>(x, W);
    k_finalize<<<1, COUT>>>(gamma, beta);
    k_pool<<<NQ / 4, 256>>>(out);
}